// round 17
// baseline (speedup 1.0000x reference)
#include <cuda_runtime.h>
#include <cuda_fp16.h>
#include <cstdint>

// GCMCGraphConv fused kernel v14 (sm_100a)
//
//   pa = sigmoid(feat @ prob_w.T); rs = sigmoid(feat @ rsw.T)
//   rf = (feat @ review_w.T) * rs
//   out[d] += (weight[src]*pa + rf) * cj[src] * ci[d]
//
// v14 = v10 (151us, reproduced 3x) with ONE change: the 16-deep A-burst
// issues BEFORE the meta chain (idx -> cj/ci gather) instead of after its
// __syncwarp. In v10 the two ~600cyc latency chains run in series at each
// tile top; here the meta gathers proceed while the A LDGs are in flight.
// Unlike v6 (meta held in regs through the GEMM -> pressure regression),
// meta is still committed to smem before the GEMM reads ccb/rbuf.
// Everything else byte-identical to v10.

#define OUT_DIM 64
#define THREADS 256
#define WARPS   8
#define TILE_E  256
#define NT      9

// per-warp: cbuf 32 rows x 32 half2 (4096B) + rbuf 32xfloat4 (512B) + ccb (128B)
#define WBUF_BYTES  (4096 + 512 + 128)
#define BTAB_OFF    (WARPS * WBUF_BYTES)
#define SMEM_BYTES  (BTAB_OFF + NT * 4 * 32 * 8)

__device__ __forceinline__ void mma16816(float c[4],
    unsigned a0, unsigned a1, unsigned a2, unsigned a3,
    unsigned b0, unsigned b1)
{
    asm volatile(
      "mma.sync.aligned.m16n8k16.row.col.f32.f16.f16.f32 "
      "{%0,%1,%2,%3}, {%4,%5,%6,%7}, {%8,%9}, {%0,%1,%2,%3};\n"
      : "+f"(c[0]), "+f"(c[1]), "+f"(c[2]), "+f"(c[3])
      : "r"(a0), "r"(a1), "r"(a2), "r"(a3), "r"(b0), "r"(b1));
}

__device__ __forceinline__ void red_add_v4(float* p, float4 v) {
    asm volatile("red.global.add.v4.f32 [%0], {%1,%2,%3,%4};"
                 :: "l"(p), "f"(v.x), "f"(v.y), "f"(v.z), "f"(v.w) : "memory");
}

__device__ __forceinline__ unsigned packh2(float a, float b) {
    __half2 h = __floats2half2_rn(a, b);
    return *(unsigned*)&h;
}
__device__ __forceinline__ float2 h2f2(unsigned u) {
    __half2 h = *(__half2*)&u;
    return __half22float2(h);
}
__device__ __forceinline__ float sigmoidf_(float x) {
    return 1.f / (1.f + __expf(-x));
}

__global__ void __launch_bounds__(THREADS, 3)
gcmc_kernel(const float* __restrict__ weight,      // [N_SRC,64]
            const float* __restrict__ prob_w,      // [64]
            const float* __restrict__ rsw,         // [64]
            const float* __restrict__ review_w,    // [64,64]
            const float* __restrict__ feat,        // [E,64]
            const float* __restrict__ cj,          // [N_SRC]
            const float* __restrict__ ci,          // [N_DST]
            const int*   __restrict__ src_idx,     // [E]
            const int*   __restrict__ dst_idx,     // [E]
            float* __restrict__ out,               // [N_DST,64]
            int E, int n_tiles)
{
    extern __shared__ char smraw[];

    const int tid  = threadIdx.x;
    const int lane = tid & 31;
    const int warp = tid >> 5;
    const int g    = lane >> 2;   // 0..7
    const int t    = lane & 3;    // 0..3

    char*   wbase = smraw + warp * WBUF_BYTES;
    unsigned* cbuf = (unsigned*)wbase;                 // [32 rows][32 half2]
    float4* rbuf = (float4*)(wbase + 4096);            // [32] {pa*cc, rs*cc, src, dst}
    float*  ccb  = (float*)(wbase + 4096 + 512);       // [32] cj*ci
    uint2 (*Btab)[4][32] = (uint2(*)[4][32])(smraw + BTAB_OFF);

    // ---- build B fragments once (fp16, single-pass; k = 16ks+4t+{0..3}) ----
    for (int i = tid; i < NT * 4 * 32; i += THREADS) {
        int l  = i & 31;
        int ks = (i >> 5) & 3;
        int nt = i >> 7;
        int gg = l >> 2, tt = l & 3;
        int k0 = 16 * ks + 4 * tt;
        float w0 = 0.f, w1 = 0.f, w2 = 0.f, w3 = 0.f;
        if (nt < 8) {
            const float* W = review_w + (nt * 8 + gg) * OUT_DIM;
            w0 = W[k0]; w1 = W[k0 + 1]; w2 = W[k0 + 2]; w3 = W[k0 + 3];
        } else if (gg == 0) {   // gate col 64 = pa (prob_w)
            w0 = prob_w[k0]; w1 = prob_w[k0 + 1];
            w2 = prob_w[k0 + 2]; w3 = prob_w[k0 + 3];
        } else if (gg == 1) {   // gate col 65 = rs (review_score_w)
            w0 = rsw[k0]; w1 = rsw[k0 + 1];
            w2 = rsw[k0 + 2]; w3 = rsw[k0 + 3];
        }
        Btab[nt][ks][l] = make_uint2(packh2(w0, w1), packh2(w2, w3));
    }
    __syncthreads();

    const int rb = warp * 32;
    const int half = lane >> 4;      // epilogue: 0/1 -> which of 2 rows
    const int j    = lane & 15;      // epilogue: 8B chunk (4 cols) within row

    for (int tile = blockIdx.x; tile < n_tiles; tile += gridDim.x) {
        const int e0 = tile * TILE_E + rb;

        // ---- issue the 16-deep A-burst FIRST (long-latency LDGs in flight) ----
        unsigned a[2][4][4];   // [mt][ks][slot], packed fp16x2
        const float* fA[2];
        const float* fB[2];
        #pragma unroll
        for (int mt = 0; mt < 2; mt++) {
            int ea = e0 + 16 * mt + g;
            int eb = ea + 8;
            fA[mt] = feat + (size_t)(ea < E ? ea : E - 1) * OUT_DIM;
            fB[mt] = feat + (size_t)(eb < E ? eb : E - 1) * OUT_DIM;
        }
        float4 v[2][4][2];
        #pragma unroll
        for (int ks = 0; ks < 4; ks++) {
            const int ko = 16 * ks + 4 * t;
            #pragma unroll
            for (int mt = 0; mt < 2; mt++) {
                v[mt][ks][0] = *(const float4*)(fA[mt] + ko);   // row g
                v[mt][ks][1] = *(const float4*)(fB[mt] + ko);   // row g+8
            }
        }

        // ---- meta chain overlaps the in-flight A loads ----
        {
            int e = e0 + lane;
            bool vd = e < E;
            int ec = vd ? e : E - 1;
            int s_ = src_idx[ec], d_ = dst_idx[ec];
            float cc = vd ? cj[s_] * ci[d_] : 0.f;
            ccb[lane] = cc;
            ((float2*)&rbuf[lane])[1] =
                make_float2(__int_as_float(s_), __int_as_float(d_));
        }

        // ---- pack A fragments (consumes the landed loads) ----
        #pragma unroll
        for (int ks = 0; ks < 4; ks++) {
            #pragma unroll
            for (int mt = 0; mt < 2; mt++) {
                a[mt][ks][0] = packh2(v[mt][ks][0].x, v[mt][ks][0].y);
                a[mt][ks][1] = packh2(v[mt][ks][1].x, v[mt][ks][1].y);
                a[mt][ks][2] = packh2(v[mt][ks][0].z, v[mt][ks][0].w);
                a[mt][ks][3] = packh2(v[mt][ks][1].z, v[mt][ks][1].w);
            }
        }
        __syncwarp();   // ccb/rbuf visible to all lanes before gate tile

        // ---- GEMM nt-outer, single-pass: 8 accum floats live ----
        #pragma unroll
        for (int nt = 0; nt < NT; nt++) {
            float c0[4] = {0.f, 0.f, 0.f, 0.f};
            float c1[4] = {0.f, 0.f, 0.f, 0.f};
            #pragma unroll
            for (int ks = 0; ks < 4; ks++) {
                uint2 b = Btab[nt][ks][lane];
                mma16816(c0, a[0][ks][0], a[0][ks][1], a[0][ks][2], a[0][ks][3], b.x, b.y);
                mma16816(c1, a[1][ks][0], a[1][ks][1], a[1][ks][2], a[1][ks][3], b.x, b.y);
            }
            if (nt < 8) {
                // slot ch2 = (4nt + t + 4*(r&3)) & 31; one half2 (2 cols) per slot
                {
                    const int r0 = g;
                    const int ch2 = (4 * nt + t + 4 * (r0 & 3)) & 31;
                    cbuf[r0 * 32 + ch2]       = packh2(c0[0], c0[1]);
                    cbuf[(r0 + 8) * 32 + ch2] = packh2(c0[2], c0[3]);
                }
                {
                    const int r0 = 16 + g;
                    const int ch2 = (4 * nt + t + 4 * (r0 & 3)) & 31;
                    cbuf[r0 * 32 + ch2]       = packh2(c1[0], c1[1]);
                    cbuf[(r0 + 8) * 32 + ch2] = packh2(c1[2], c1[3]);
                }
            } else if (t == 0) {
                // gate tile: cols 64(pa), 65(rs); fold sigmoid * cjci
                {
                    const int r0 = g, r1 = g + 8;
                    float cc0 = ccb[r0], cc1 = ccb[r1];
                    ((float2*)&rbuf[r0])[0] = make_float2(
                        sigmoidf_(c0[0]) * cc0, sigmoidf_(c0[1]) * cc0);
                    ((float2*)&rbuf[r1])[0] = make_float2(
                        sigmoidf_(c0[2]) * cc1, sigmoidf_(c0[3]) * cc1);
                }
                {
                    const int r0 = 16 + g, r1 = 24 + g;
                    float cc0 = ccb[r0], cc1 = ccb[r1];
                    ((float2*)&rbuf[r0])[0] = make_float2(
                        sigmoidf_(c1[0]) * cc0, sigmoidf_(c1[1]) * cc0);
                    ((float2*)&rbuf[r1])[0] = make_float2(
                        sigmoidf_(c1[2]) * cc1, sigmoidf_(c1[3]) * cc1);
                }
            }
        }
        __syncwarp();

        // ---- row-major epilogue: 2 edge rows per warp instruction ----
        #pragma unroll
        for (int i = 0; i < 16; i++) {
            const int r = 2 * i + half;
            // slots {2j, 2j+1} = 2 half2 = 4 columns
            uint2 cp = *(const uint2*)(cbuf + r * 32 + 2 * j);
            float2 lo = h2f2(cp.x), hi = h2f2(cp.y);
            const int cn2 = (2 * j - 4 * (r & 3)) & 31;   // even, no pair wrap
            const int col = 2 * cn2;                       // 16B aligned
            float4 q = rbuf[r];                            // {paC, rsC, src, dst}
            int sx = __float_as_int(q.z);
            int dx = __float_as_int(q.w);
            float4 wv = *(const float4*)(weight + (size_t)sx * OUT_DIM + col);
            float4 o;
            o.x = fmaf(wv.x, q.x, lo.x * q.y);
            o.y = fmaf(wv.y, q.x, lo.y * q.y);
            o.z = fmaf(wv.z, q.x, hi.x * q.y);
            o.w = fmaf(wv.w, q.x, hi.y * q.y);
            red_add_v4(out + (size_t)dx * OUT_DIM + col, o);
        }
        __syncwarp();   // buffers reused next tile (warp-private)
    }
}

extern "C" void kernel_launch(void* const* d_in, const int* in_sizes, int n_in,
                              void* d_out, int out_size) {
    const float* weight   = (const float*)d_in[0];
    const float* prob_w   = (const float*)d_in[1];
    const float* rsw      = (const float*)d_in[2];
    const float* review_w = (const float*)d_in[3];
    const float* feat     = (const float*)d_in[4];
    const float* cj       = (const float*)d_in[5];
    const float* ci       = (const float*)d_in[6];
    const int*   src_idx  = (const int*)d_in[7];
    const int*   dst_idx  = (const int*)d_in[8];
    float* out = (float*)d_out;

    const int E = in_sizes[4] / OUT_DIM;
    const int n_tiles = (E + TILE_E - 1) / TILE_E;

    cudaMemsetAsync(d_out, 0, (size_t)out_size * sizeof(float), 0);

    static int smem_set = 0;
    if (!smem_set) {
        cudaFuncSetAttribute(gcmc_kernel,
                             cudaFuncAttributeMaxDynamicSharedMemorySize,
                             SMEM_BYTES);
        smem_set = 1;
    }

    int grid = n_tiles < 444 ? n_tiles : 444;   // 3 persistent blocks / SM
    gcmc_kernel<<<grid, THREADS, SMEM_BYTES, 0>>>(
        weight, prob_w, rsw, review_w, feat, cj, ci, src_idx, dst_idx,
        out, E, n_tiles);
}